// round 16
// baseline (speedup 1.0000x reference)
#include <cuda_runtime.h>
#include <cuda_fp16.h>

#define N_NODES  100000
#define N_EDGES  600000

typedef unsigned long long ull;
typedef unsigned int u32;

// Scratch (fp16): Y[n][0:128] = x[n]@W_i + b, Y[n][128:256] = x[n]@W_j
__device__ __align__(16) __half g_Y[(size_t)N_NODES * 256];
// W_i/W_j in fp16, transposed: g_Wt[h][n][k] = W[h*128 + k][n]
__device__ __align__(16) __half g_Wt[2 * 128 * 128];
// W_e in fp16, transposed: g_Wet[n][k] = W[256 + k][n]  (128 x 16)
__device__ __align__(16) __half g_Wet[128 * 16];

// ---------------------------------------------------------------------------
// Weight prep: 32x32 smem transpose, coalesced reads AND writes.
// ---------------------------------------------------------------------------
__global__ void prep_W(const float* __restrict__ W) {
    __shared__ float tile[32][33];
    const int tx = threadIdx.x & 31;
    const int ty = threadIdx.x >> 5;
    const int k0 = blockIdx.x * 32;
    const int n0 = blockIdx.y * 32;

    #pragma unroll
    for (int i = 0; i < 4; i++) {
        int r = k0 + ty + 8 * i;
        float v = 0.f;
        if (r < 272) v = W[r * 128 + n0 + tx];
        tile[ty + 8 * i][tx] = v;
    }
    __syncthreads();

    #pragma unroll
    for (int i = 0; i < 4; i++) {
        int n = n0 + ty + 8 * i;
        int k = k0 + tx;
        __half v = __float2half(tile[tx][ty + 8 * i]);
        if (k < 256) {
            int h = k >> 7, kk = k & 127;
            g_Wt[h * 16384 + n * 128 + kk] = v;
        } else if (k < 272) {
            g_Wet[n * 16 + (k - 256)] = v;
        }
    }
}

// ---------------------------------------------------------------------------
__device__ __forceinline__ void ldsm_x4(u32 addr, u32& r0, u32& r1, u32& r2, u32& r3) {
    asm volatile("ldmatrix.sync.aligned.m8n8.x4.shared.b16 {%0,%1,%2,%3}, [%4];"
                 : "=r"(r0), "=r"(r1), "=r"(r2), "=r"(r3) : "r"(addr));
}
__device__ __forceinline__ void mma16816(float* c, const u32* a, u32 b0, u32 b1) {
    asm volatile("mma.sync.aligned.m16n8k16.row.col.f32.f16.f16.f32 "
                 "{%0,%1,%2,%3}, {%4,%5,%6,%7}, {%8,%9}, {%0,%1,%2,%3};"
                 : "+f"(c[0]), "+f"(c[1]), "+f"(c[2]), "+f"(c[3])
                 : "r"(a[0]), "r"(a[1]), "r"(a[2]), "r"(a[3]), "r"(b0), "r"(b1));
}
__device__ __forceinline__ void stg_cs(float* p, float4 v) {
    asm volatile("st.global.cs.v4.f32 [%0], {%1,%2,%3,%4};"
                 :: "l"(p), "f"(v.x), "f"(v.y), "f"(v.z), "f"(v.w) : "memory");
}

#define LDA 136  // node-GEMM smem stride (halfs)

// ---------------------------------------------------------------------------
// Node GEMM: BM=64, BN=128, K=128. grid = (2, 1563), 256 threads.
// smem 52.2 KB -> 4 CTAs/SM (32 warps); acc[8][4] -> ~60 regs.
// 8 warps in 4(m) x 2(n); per-warp tile m16 x n64.
// ---------------------------------------------------------------------------
__global__ void __launch_bounds__(256) gemm_mma(const float* __restrict__ x,
                                                const float* __restrict__ b) {
    extern __shared__ __half sh[];
    __half* As = sh;              // [64][136]
    __half* Bs = sh + 64 * LDA;   // [128][136]

    const int tid = threadIdx.x;
    const int h   = blockIdx.x;
    const int n0  = h << 7;
    const int m0  = blockIdx.y << 6;

    // Bs <- g_Wt half (32KB straight copy)
    {
        const uint4* src = (const uint4*)(g_Wt + h * 16384);
        #pragma unroll
        for (int p = 0; p < 8; p++) {
            int idx = tid + p * 256;
            int n = idx >> 4, c8 = idx & 15;
            *(uint4*)(Bs + n * LDA + c8 * 8) = src[idx];
        }
    }
    // As <- fp16(x[m0..m0+63][:]), zero past N_NODES
    {
        const float4* x4 = (const float4*)x;
        #pragma unroll
        for (int p = 0; p < 8; p++) {
            int idx = tid + p * 256;
            int row = idx >> 5, c4 = idx & 31;
            float4 v = make_float4(0.f, 0.f, 0.f, 0.f);
            if (m0 + row < N_NODES) v = x4[(size_t)(m0 + row) * 32 + c4];
            __half2 h0 = __floats2half2_rn(v.x, v.y);
            __half2 h1 = __floats2half2_rn(v.z, v.w);
            uint2 u; u.x = *(u32*)&h0; u.y = *(u32*)&h1;
            *(uint2*)(As + row * LDA + c4 * 4) = u;
        }
    }
    __syncthreads();

    const int lane   = tid & 31;
    const int wid    = tid >> 5;
    const int warp_m = wid >> 1;    // 0..3, m offset 16*warp_m
    const int warp_n = wid & 1;     // n offset 64*warp_n

    float acc[8][4];
    #pragma unroll
    for (int nt = 0; nt < 8; nt++)
        #pragma unroll
        for (int i = 0; i < 4; i++) acc[nt][i] = 0.f;

    const int lr = lane & 15;
    const int lc = (lane >> 4) << 3;
    const u32 aBase = (u32)__cvta_generic_to_shared(As)
                      + ((warp_m * 16 + lr) * LDA + lc) * 2;
    const u32 bBase = (u32)__cvta_generic_to_shared(Bs)
                      + ((warp_n * 64 + lr) * LDA + lc) * 2;

    #pragma unroll
    for (int ks = 0; ks < 8; ks++) {
        u32 a[4];
        ldsm_x4(aBase + ks * 32, a[0], a[1], a[2], a[3]);
        u32 br[4][4];
        #pragma unroll
        for (int q = 0; q < 4; q++)
            ldsm_x4(bBase + q * 16 * LDA * 2 + ks * 32,
                    br[q][0], br[q][1], br[q][2], br[q][3]);
        #pragma unroll
        for (int q = 0; q < 4; q++) {
            mma16816(acc[2 * q],     a, br[q][0], br[q][2]);
            mma16816(acc[2 * q + 1], a, br[q][1], br[q][3]);
        }
    }

    const int gr = lane >> 2;
    const int gc = (lane & 3) * 2;
    {
        int r0 = m0 + warp_m * 16 + gr;
        #pragma unroll
        for (int nt = 0; nt < 8; nt++) {
            int cb = warp_n * 64 + nt * 8 + gc;
            float b0 = 0.f, b1 = 0.f;
            if (h == 0) { b0 = b[cb]; b1 = b[cb + 1]; }
            if (r0 < N_NODES) {
                __half2 v = __floats2half2_rn(acc[nt][0] + b0, acc[nt][1] + b1);
                *(__half2*)(g_Y + (size_t)r0 * 256 + n0 + cb) = v;
            }
            if (r0 + 8 < N_NODES) {
                __half2 v = __floats2half2_rn(acc[nt][2] + b0, acc[nt][3] + b1);
                *(__half2*)(g_Y + (size_t)(r0 + 8) * 256 + n0 + cb) = v;
            }
        }
    }
}

// ---------------------------------------------------------------------------
// Fused edge kernel (R15 + st.global.cs out stores): 128 edges per block.
// ---------------------------------------------------------------------------
#define EW  24   // edge_attr / W_e smem stride (halfs)
#define SAW 132  // sAcc stride (halfs)

__global__ void __launch_bounds__(256)
edge_fused(const int* __restrict__ ei,
           const float* __restrict__ edge_attr,
           float* __restrict__ out) {
    extern __shared__ __half smem_h[];
    __half* sAcc = smem_h;                        // [128][132] fp16
    __half* sEA  = sAcc + 128 * SAW;              // [128][EW]
    __half* sWe  = sEA + 128 * EW;                // [128][EW]
    int*    sIdx = (int*)(sWe + 128 * EW);        // [256]

    const int tid = threadIdx.x;
    const int e0  = blockIdx.x * 128;

    // W_e^T tile
    {
        int n = tid >> 1, part = tid & 1;
        *(uint4*)(sWe + n * EW + part * 8) = ((const uint4*)g_Wet)[tid];
    }
    // edge_attr tile -> fp16, zero-pad past N_EDGES
    {
        #pragma unroll
        for (int p = 0; p < 2; p++) {
            int idx = tid + p * 256;
            int row = idx >> 2, q = idx & 3;
            float4 v = make_float4(0.f, 0.f, 0.f, 0.f);
            if (e0 + row < N_EDGES)
                v = ((const float4*)edge_attr)[(size_t)(e0 + row) * 4 + q];
            __half2 h0 = __floats2half2_rn(v.x, v.y);
            __half2 h1 = __floats2half2_rn(v.z, v.w);
            uint2 u; u.x = *(u32*)&h0; u.y = *(u32*)&h1;
            *(uint2*)(sEA + row * EW + q * 4) = u;
        }
    }
    // indices
    {
        int row = tid & 127;
        int side = tid >> 7;
        int v = 0;
        if (e0 + row < N_EDGES) v = ei[(size_t)side * N_EDGES + e0 + row];
        sIdx[side * 128 + row] = v;
    }
    __syncthreads();

    const int lane   = tid & 31;
    const int wid    = tid >> 5;
    const int warp_m = wid >> 1;
    const int warp_n = wid & 1;
    const int row0   = wid * 16;

    // --- prefetch gathers for edges row0..row0+2 (fly during MMA) ---
    uint2 ga[3], gb[3];
    #pragma unroll
    for (int j = 0; j < 3; j++) {
        int s = sIdx[row0 + j];
        int t = sIdx[128 + row0 + j];
        ga[j] = *(const uint2*)(g_Y + (size_t)s * 256 + lane * 4);
        gb[j] = *(const uint2*)(g_Y + (size_t)t * 256 + 128 + lane * 4);
    }

    // ---- MMA: one m16n8k16 k-step ----
    float acc[2][8][4];
    #pragma unroll
    for (int mt = 0; mt < 2; mt++)
        #pragma unroll
        for (int nt = 0; nt < 8; nt++)
            #pragma unroll
            for (int i = 0; i < 4; i++) acc[mt][nt][i] = 0.f;

    {
        const int lr = lane & 15;
        const int lc = (lane >> 4) << 3;
        const u32 aBase = (u32)__cvta_generic_to_shared(sEA)
                          + ((warp_m * 32 + lr) * EW + lc) * 2;
        const u32 bBase = (u32)__cvta_generic_to_shared(sWe)
                          + ((warp_n * 64 + lr) * EW + lc) * 2;
        u32 a[2][4];
        ldsm_x4(aBase,               a[0][0], a[0][1], a[0][2], a[0][3]);
        ldsm_x4(aBase + 16 * EW * 2, a[1][0], a[1][1], a[1][2], a[1][3]);
        u32 br[4][4];
        #pragma unroll
        for (int q = 0; q < 4; q++)
            ldsm_x4(bBase + q * 16 * EW * 2,
                    br[q][0], br[q][1], br[q][2], br[q][3]);
        #pragma unroll
        for (int mt = 0; mt < 2; mt++)
            #pragma unroll
            for (int q = 0; q < 4; q++) {
                mma16816(acc[mt][2 * q],     a[mt], br[q][0], br[q][2]);
                mma16816(acc[mt][2 * q + 1], a[mt], br[q][1], br[q][3]);
            }
    }

    // stage acc -> smem (fp16)
    {
        const int gr = lane >> 2;
        const int gc = (lane & 3) * 2;
        #pragma unroll
        for (int mt = 0; mt < 2; mt++) {
            int r0 = warp_m * 32 + mt * 16 + gr;
            #pragma unroll
            for (int nt = 0; nt < 8; nt++) {
                int cb = warp_n * 64 + nt * 8 + gc;
                __half2 v0 = __floats2half2_rn(acc[mt][nt][0], acc[mt][nt][1]);
                __half2 v1 = __floats2half2_rn(acc[mt][nt][2], acc[mt][nt][3]);
                *(__half2*)(sAcc + r0 * SAW + cb) = v0;
                *(__half2*)(sAcc + (r0 + 8) * SAW + cb) = v1;
            }
        }
    }
    __syncthreads();

    // ---- Epilogue: 16 edges per warp, depth-3 pipeline, .cs stores ----
    #pragma unroll
    for (int i = 0; i < 16; i++) {
        int r = row0 + i;
        int e = e0 + r;
        int slot = i % 3;

        uint2 nga, ngb;
        if (i + 3 < 16) {
            int ns = sIdx[r + 3];
            int nt = sIdx[128 + r + 3];
            nga = *(const uint2*)(g_Y + (size_t)ns * 256 + lane * 4);
            ngb = *(const uint2*)(g_Y + (size_t)nt * 256 + 128 + lane * 4);
        } else {
            nga = ga[slot]; ngb = gb[slot];
        }

        if (e < N_EDGES) {
            uint2 ua = ga[slot], ub = gb[slot];
            uint2 uc = *(const uint2*)(sAcc + r * SAW + lane * 4);
            float2 a0 = __half22float2(*(__half2*)&ua.x);
            float2 a1 = __half22float2(*(__half2*)&ua.y);
            float2 b0 = __half22float2(*(__half2*)&ub.x);
            float2 b1 = __half22float2(*(__half2*)&ub.y);
            float2 c0 = __half22float2(*(__half2*)&uc.x);
            float2 c1 = __half22float2(*(__half2*)&uc.y);
            float4 r4;
            r4.x = c0.x + a0.x + b0.x;
            r4.y = c0.y + a0.y + b0.y;
            r4.z = c1.x + a1.x + b1.x;
            r4.w = c1.y + a1.y + b1.y;
            stg_cs(out + (size_t)e * 128 + lane * 4, r4);
        }
        ga[slot] = nga;
        gb[slot] = ngb;
    }
}

// ---------------------------------------------------------------------------
extern "C" void kernel_launch(void* const* d_in, const int* in_sizes, int n_in,
                              void* d_out, int out_size) {
    const float* x  = (const float*)d_in[0];
    const int*   ei = (const int*)d_in[1];
    const float* ea = (const float*)d_in[2];
    const float* W  = (const float*)d_in[3];
    const float* b  = (const float*)d_in[4];
    float* out = (float*)d_out;

    const int gemm_smem = (64 + 128) * LDA * (int)sizeof(__half);    // 52224
    cudaFuncSetAttribute(gemm_mma,
                         cudaFuncAttributeMaxDynamicSharedMemorySize, gemm_smem);
    const int edge_smem = (128 * SAW + 2 * 128 * EW) * 2 + 256 * 4;  // 47104
    cudaFuncSetAttribute(edge_fused,
                         cudaFuncAttributeMaxDynamicSharedMemorySize, edge_smem);

    prep_W<<<dim3(9, 4), 256>>>(W);
    gemm_mma<<<dim3(2, (N_NODES + 63) / 64), 256, gemm_smem>>>(x, b);
    edge_fused<<<(N_EDGES + 127) / 128, 256, edge_smem>>>(ei, ea, out);
}

// round 17
// speedup vs baseline: 1.0598x; 1.0598x over previous
#include <cuda_runtime.h>
#include <cuda_fp16.h>

#define N_NODES  100000
#define N_EDGES  600000

typedef unsigned long long ull;
typedef unsigned int u32;

// Scratch (fp16): Y[n][0:128] = x[n]@W_i + b, Y[n][128:256] = x[n]@W_j
__device__ __align__(16) __half g_Y[(size_t)N_NODES * 256];
// W_i/W_j in fp16, transposed: g_Wt[h][n][k] = W[h*128 + k][n]
__device__ __align__(16) __half g_Wt[2 * 128 * 128];
// W_e in fp16, transposed: g_Wet[n][k] = W[256 + k][n]  (128 x 16)
__device__ __align__(16) __half g_Wet[128 * 16];

// ---------------------------------------------------------------------------
// Weight prep: 32x32 smem transpose, coalesced reads AND writes.
// ---------------------------------------------------------------------------
__global__ void prep_W(const float* __restrict__ W) {
    __shared__ float tile[32][33];
    const int tx = threadIdx.x & 31;
    const int ty = threadIdx.x >> 5;
    const int k0 = blockIdx.x * 32;
    const int n0 = blockIdx.y * 32;

    #pragma unroll
    for (int i = 0; i < 4; i++) {
        int r = k0 + ty + 8 * i;
        float v = 0.f;
        if (r < 272) v = W[r * 128 + n0 + tx];
        tile[ty + 8 * i][tx] = v;
    }
    __syncthreads();

    #pragma unroll
    for (int i = 0; i < 4; i++) {
        int n = n0 + ty + 8 * i;
        int k = k0 + tx;
        __half v = __float2half(tile[tx][ty + 8 * i]);
        if (k < 256) {
            int h = k >> 7, kk = k & 127;
            g_Wt[h * 16384 + n * 128 + kk] = v;
        } else if (k < 272) {
            g_Wet[n * 16 + (k - 256)] = v;
        }
    }
}

// ---------------------------------------------------------------------------
__device__ __forceinline__ void ldsm_x4(u32 addr, u32& r0, u32& r1, u32& r2, u32& r3) {
    asm volatile("ldmatrix.sync.aligned.m8n8.x4.shared.b16 {%0,%1,%2,%3}, [%4];"
                 : "=r"(r0), "=r"(r1), "=r"(r2), "=r"(r3) : "r"(addr));
}
__device__ __forceinline__ void mma16816(float* c, const u32* a, u32 b0, u32 b1) {
    asm volatile("mma.sync.aligned.m16n8k16.row.col.f32.f16.f16.f32 "
                 "{%0,%1,%2,%3}, {%4,%5,%6,%7}, {%8,%9}, {%0,%1,%2,%3};"
                 : "+f"(c[0]), "+f"(c[1]), "+f"(c[2]), "+f"(c[3])
                 : "r"(a[0]), "r"(a[1]), "r"(a[2]), "r"(a[3]), "r"(b0), "r"(b1));
}
__device__ __forceinline__ void cp_async16(u32 smem_addr, const void* gptr) {
    asm volatile("cp.async.cg.shared.global [%0], [%1], 16;"
                 :: "r"(smem_addr), "l"(gptr));
}

#define LDA 136  // node-GEMM smem stride (halfs)

// ---------------------------------------------------------------------------
// Node GEMM (R8/R15 structure + cp.async Bs prologue):
// BM=128, BN=128, K=128. grid = (2, 782), 256 threads, 3 CTAs/SM.
// ---------------------------------------------------------------------------
__global__ void __launch_bounds__(256) gemm_mma(const float* __restrict__ x,
                                                const float* __restrict__ b) {
    extern __shared__ __half sh[];
    __half* As = sh;               // [128][136]
    __half* Bs = sh + 128 * LDA;   // [128][136]

    const int tid = threadIdx.x;
    const int h   = blockIdx.x;
    const int n0  = h << 7;
    const int m0  = blockIdx.y << 7;

    // Bs <- g_Wt half via cp.async (fp16 already; fire-and-forget)
    {
        const uint4* src = (const uint4*)(g_Wt + h * 16384);
        const u32 bs = (u32)__cvta_generic_to_shared(Bs);
        #pragma unroll
        for (int p = 0; p < 8; p++) {
            int idx = tid + p * 256;
            int n = idx >> 4, c8 = idx & 15;
            cp_async16(bs + (n * LDA + c8 * 8) * 2, src + idx);
        }
        asm volatile("cp.async.commit_group;");
    }
    // As <- fp16(x[m0..m0+127][:]) — runs while Bs streams in
    {
        const float4* x4 = (const float4*)x;
        #pragma unroll
        for (int p = 0; p < 16; p++) {
            int idx = tid + p * 256;
            int row = idx >> 5, c4 = idx & 31;
            float4 v = make_float4(0.f, 0.f, 0.f, 0.f);
            if (m0 + row < N_NODES) v = x4[(size_t)(m0 + row) * 32 + c4];
            __half2 h0 = __floats2half2_rn(v.x, v.y);
            __half2 h1 = __floats2half2_rn(v.z, v.w);
            uint2 u; u.x = *(u32*)&h0; u.y = *(u32*)&h1;
            *(uint2*)(As + row * LDA + c4 * 4) = u;
        }
    }
    asm volatile("cp.async.wait_group 0;");
    __syncthreads();

    const int lane   = tid & 31;
    const int wid    = tid >> 5;
    const int warp_m = wid >> 1;
    const int warp_n = wid & 1;

    float acc[2][8][4];
    #pragma unroll
    for (int mt = 0; mt < 2; mt++)
        #pragma unroll
        for (int nt = 0; nt < 8; nt++)
            #pragma unroll
            for (int i = 0; i < 4; i++) acc[mt][nt][i] = 0.f;

    const int lr = lane & 15;
    const int lc = (lane >> 4) << 3;
    const u32 aBase = (u32)__cvta_generic_to_shared(As)
                      + ((warp_m * 32 + lr) * LDA + lc) * 2;
    const u32 bBase = (u32)__cvta_generic_to_shared(Bs)
                      + ((warp_n * 64 + lr) * LDA + lc) * 2;

    #pragma unroll
    for (int ks = 0; ks < 8; ks++) {
        u32 a[2][4];
        ldsm_x4(aBase + ks * 32,                a[0][0], a[0][1], a[0][2], a[0][3]);
        ldsm_x4(aBase + 16 * LDA * 2 + ks * 32, a[1][0], a[1][1], a[1][2], a[1][3]);
        u32 br[4][4];
        #pragma unroll
        for (int q = 0; q < 4; q++)
            ldsm_x4(bBase + q * 16 * LDA * 2 + ks * 32,
                    br[q][0], br[q][1], br[q][2], br[q][3]);
        #pragma unroll
        for (int mt = 0; mt < 2; mt++)
            #pragma unroll
            for (int q = 0; q < 4; q++) {
                mma16816(acc[mt][2 * q],     a[mt], br[q][0], br[q][2]);
                mma16816(acc[mt][2 * q + 1], a[mt], br[q][1], br[q][3]);
            }
    }

    const int gr = lane >> 2;
    const int gc = (lane & 3) * 2;
    #pragma unroll
    for (int mt = 0; mt < 2; mt++) {
        int r0 = m0 + warp_m * 32 + mt * 16 + gr;
        #pragma unroll
        for (int nt = 0; nt < 8; nt++) {
            int cb = warp_n * 64 + nt * 8 + gc;
            float b0 = 0.f, b1 = 0.f;
            if (h == 0) { b0 = b[cb]; b1 = b[cb + 1]; }
            if (r0 < N_NODES) {
                __half2 v = __floats2half2_rn(acc[mt][nt][0] + b0,
                                              acc[mt][nt][1] + b1);
                *(__half2*)(g_Y + (size_t)r0 * 256 + n0 + cb) = v;
            }
            if (r0 + 8 < N_NODES) {
                __half2 v = __floats2half2_rn(acc[mt][nt][2] + b0,
                                              acc[mt][nt][3] + b1);
                *(__half2*)(g_Y + (size_t)(r0 + 8) * 256 + n0 + cb) = v;
            }
        }
    }
}

// ---------------------------------------------------------------------------
// Fused edge kernel (R15-exact): 128 edges per block, depth-3 pipeline.
// ---------------------------------------------------------------------------
#define EW  24   // edge_attr / W_e smem stride (halfs)
#define SAW 132  // sAcc stride (halfs)

__global__ void __launch_bounds__(256)
edge_fused(const int* __restrict__ ei,
           const float* __restrict__ edge_attr,
           float* __restrict__ out) {
    extern __shared__ __half smem_h[];
    __half* sAcc = smem_h;                        // [128][132] fp16
    __half* sEA  = sAcc + 128 * SAW;              // [128][EW]
    __half* sWe  = sEA + 128 * EW;                // [128][EW]
    int*    sIdx = (int*)(sWe + 128 * EW);        // [256]

    const int tid = threadIdx.x;
    const int e0  = blockIdx.x * 128;

    // W_e^T tile
    {
        int n = tid >> 1, part = tid & 1;
        *(uint4*)(sWe + n * EW + part * 8) = ((const uint4*)g_Wet)[tid];
    }
    // edge_attr tile -> fp16, zero-pad past N_EDGES
    {
        #pragma unroll
        for (int p = 0; p < 2; p++) {
            int idx = tid + p * 256;
            int row = idx >> 2, q = idx & 3;
            float4 v = make_float4(0.f, 0.f, 0.f, 0.f);
            if (e0 + row < N_EDGES)
                v = ((const float4*)edge_attr)[(size_t)(e0 + row) * 4 + q];
            __half2 h0 = __floats2half2_rn(v.x, v.y);
            __half2 h1 = __floats2half2_rn(v.z, v.w);
            uint2 u; u.x = *(u32*)&h0; u.y = *(u32*)&h1;
            *(uint2*)(sEA + row * EW + q * 4) = u;
        }
    }
    // indices
    {
        int row = tid & 127;
        int side = tid >> 7;
        int v = 0;
        if (e0 + row < N_EDGES) v = ei[(size_t)side * N_EDGES + e0 + row];
        sIdx[side * 128 + row] = v;
    }
    __syncthreads();

    const int lane   = tid & 31;
    const int wid    = tid >> 5;
    const int warp_m = wid >> 1;
    const int warp_n = wid & 1;
    const int row0   = wid * 16;

    // --- prefetch gathers for edges row0..row0+2 (fly during MMA) ---
    uint2 ga[3], gb[3];
    #pragma unroll
    for (int j = 0; j < 3; j++) {
        int s = sIdx[row0 + j];
        int t = sIdx[128 + row0 + j];
        ga[j] = *(const uint2*)(g_Y + (size_t)s * 256 + lane * 4);
        gb[j] = *(const uint2*)(g_Y + (size_t)t * 256 + 128 + lane * 4);
    }

    // ---- MMA: one m16n8k16 k-step ----
    float acc[2][8][4];
    #pragma unroll
    for (int mt = 0; mt < 2; mt++)
        #pragma unroll
        for (int nt = 0; nt < 8; nt++)
            #pragma unroll
            for (int i = 0; i < 4; i++) acc[mt][nt][i] = 0.f;

    {
        const int lr = lane & 15;
        const int lc = (lane >> 4) << 3;
        const u32 aBase = (u32)__cvta_generic_to_shared(sEA)
                          + ((warp_m * 32 + lr) * EW + lc) * 2;
        const u32 bBase = (u32)__cvta_generic_to_shared(sWe)
                          + ((warp_n * 64 + lr) * EW + lc) * 2;
        u32 a[2][4];
        ldsm_x4(aBase,               a[0][0], a[0][1], a[0][2], a[0][3]);
        ldsm_x4(aBase + 16 * EW * 2, a[1][0], a[1][1], a[1][2], a[1][3]);
        u32 br[4][4];
        #pragma unroll
        for (int q = 0; q < 4; q++)
            ldsm_x4(bBase + q * 16 * EW * 2,
                    br[q][0], br[q][1], br[q][2], br[q][3]);
        #pragma unroll
        for (int mt = 0; mt < 2; mt++)
            #pragma unroll
            for (int q = 0; q < 4; q++) {
                mma16816(acc[mt][2 * q],     a[mt], br[q][0], br[q][2]);
                mma16816(acc[mt][2 * q + 1], a[mt], br[q][1], br[q][3]);
            }
    }

    // stage acc -> smem (fp16)
    {
        const int gr = lane >> 2;
        const int gc = (lane & 3) * 2;
        #pragma unroll
        for (int mt = 0; mt < 2; mt++) {
            int r0 = warp_m * 32 + mt * 16 + gr;
            #pragma unroll
            for (int nt = 0; nt < 8; nt++) {
                int cb = warp_n * 64 + nt * 8 + gc;
                __half2 v0 = __floats2half2_rn(acc[mt][nt][0], acc[mt][nt][1]);
                __half2 v1 = __floats2half2_rn(acc[mt][nt][2], acc[mt][nt][3]);
                *(__half2*)(sAcc + r0 * SAW + cb) = v0;
                *(__half2*)(sAcc + (r0 + 8) * SAW + cb) = v1;
            }
        }
    }
    __syncthreads();

    // ---- Epilogue: 16 edges per warp, depth-3 pipeline ----
    #pragma unroll
    for (int i = 0; i < 16; i++) {
        int r = row0 + i;
        int e = e0 + r;
        int slot = i % 3;

        uint2 nga, ngb;
        if (i + 3 < 16) {
            int ns = sIdx[r + 3];
            int nt = sIdx[128 + r + 3];
            nga = *(const uint2*)(g_Y + (size_t)ns * 256 + lane * 4);
            ngb = *(const uint2*)(g_Y + (size_t)nt * 256 + 128 + lane * 4);
        } else {
            nga = ga[slot]; ngb = gb[slot];
        }

        if (e < N_EDGES) {
            uint2 ua = ga[slot], ub = gb[slot];
            uint2 uc = *(const uint2*)(sAcc + r * SAW + lane * 4);
            float2 a0 = __half22float2(*(__half2*)&ua.x);
            float2 a1 = __half22float2(*(__half2*)&ua.y);
            float2 b0 = __half22float2(*(__half2*)&ub.x);
            float2 b1 = __half22float2(*(__half2*)&ub.y);
            float2 c0 = __half22float2(*(__half2*)&uc.x);
            float2 c1 = __half22float2(*(__half2*)&uc.y);
            float4 r4;
            r4.x = c0.x + a0.x + b0.x;
            r4.y = c0.y + a0.y + b0.y;
            r4.z = c1.x + a1.x + b1.x;
            r4.w = c1.y + a1.y + b1.y;
            *(float4*)(out + (size_t)e * 128 + lane * 4) = r4;
        }
        ga[slot] = nga;
        gb[slot] = ngb;
    }
}

// ---------------------------------------------------------------------------
extern "C" void kernel_launch(void* const* d_in, const int* in_sizes, int n_in,
                              void* d_out, int out_size) {
    const float* x  = (const float*)d_in[0];
    const int*   ei = (const int*)d_in[1];
    const float* ea = (const float*)d_in[2];
    const float* W  = (const float*)d_in[3];
    const float* b  = (const float*)d_in[4];
    float* out = (float*)d_out;

    const int gemm_smem = 2 * 128 * LDA * (int)sizeof(__half);       // 69632
    cudaFuncSetAttribute(gemm_mma,
                         cudaFuncAttributeMaxDynamicSharedMemorySize, gemm_smem);
    const int edge_smem = (128 * SAW + 2 * 128 * EW) * 2 + 256 * 4;  // 47104
    cudaFuncSetAttribute(edge_fused,
                         cudaFuncAttributeMaxDynamicSharedMemorySize, edge_smem);

    prep_W<<<dim3(9, 4), 256>>>(W);
    gemm_mma<<<dim3(2, (N_NODES + 127) / 128), 256, gemm_smem>>>(x, b);
    edge_fused<<<(N_EDGES + 127) / 128, 256, edge_smem>>>(ei, ea, out);
}